// round 7
// baseline (speedup 1.0000x reference)
#include <cuda_runtime.h>

// ============================================================================
// ImageLinearAttention — separable-factorization, fused-projection version.
//
// Shapes: B=4, C=16, T=32, H=64, W=64 (HW=4096), KD=2, NK=3*KD=6.
//
// Math (per b,c):
//   qkv_t[k,t] = sum_n x[t,n] * w_qkv_t[k,n]      (k=0..5; q=0..1, k=2..3, v=4..5)
//   qkv_s[k,n] = sum_t x[t,n] * w_qkv_s[k,t]
//   U[d,t] = sqrt(softmax_d(qt)[d,t] + eps)
//   V[d,n] = sqrt(softmax_d(qs)[d,n] + eps)
//   A[d,e] = sum_t sqrt((softmax_t(kt)[d,t]+eps) * vt[e,t])
//   Bm[d,e]= sum_n sqrt((softmax_n(ks)[d,n]+eps) * vs[e,n])
//          ~= (sum_n sqrt(exp(ks_d[n]))*sqrt(vs_e[n])) / sqrt(S_d)
//             [eps dropped inside this sqrt only; rel err ~ eps/(2p) ~ 2e-7]
//   ctx[d,e] = scale * A[d,e] * Bm[d,e]
//   Gs[c',m=(c,d)] = scale * sum_e w_out_s[c', c*2+e] * ctx[d,e]   (Gt likewise)
// Output:
//   out_s[b,c',t,n] = sum_m Gs[c',m] * U[m,t] * V[m,n]
//   final = sqrt(out_s * out_t)
//
// Stage P fuses: projections + spatial softmaxes + V + spatial k/v partials.
// In-loop warp reductions use a truncated 3-stage butterfly + 4-lane STS
// (5 SHFL -> 3 SHFL + 1 STS) to keep the MIO pipe under the DRAM floor.
// ============================================================================

#define B_   4
#define C_   16
#define T_   32
#define HW_  4096
#define NK   6
#define M_   32   // C_*KD

// Scratch (allocation-free: __device__ globals)
__device__ float g_qkv_t_part[B_ * C_ * 2 * NK * T_]; // per-half temporal partials
__device__ float g_sp[B_ * C_ * 2 * 6];               // per-half {S0,S1,P00,P01,P10,P11}
__device__ float g_V[B_ * M_ * HW_];                  // [b][m][n]   (2 MB)
__device__ float g_U[B_ * M_ * T_];                   // [b][m][t]
__device__ float g_Gs[B_ * C_ * M_];                  // [b][c'][m]
__device__ float g_Gt[B_ * C_ * M_];

__device__ __forceinline__ float warpSumAll(float v) {
    v += __shfl_xor_sync(0xffffffffu, v, 16);
    v += __shfl_xor_sync(0xffffffffu, v, 8);
    v += __shfl_xor_sync(0xffffffffu, v, 4);
    v += __shfl_xor_sync(0xffffffffu, v, 2);
    v += __shfl_xor_sync(0xffffffffu, v, 1);
    return v;
}

// Truncated butterfly: after xor 16/8/4, lanes 0..3 each hold the sum of
// their 8-lane coset {lane, lane+4, ..., lane+28}; the 4 partials sum to
// the full warp total.
__device__ __forceinline__ float warpSum4(float v) {
    v += __shfl_xor_sync(0xffffffffu, v, 16);
    v += __shfl_xor_sync(0xffffffffu, v, 8);
    v += __shfl_xor_sync(0xffffffffu, v, 4);
    return v;
}

// Packed f32x2 helpers (Blackwell fma.rn.f32x2 — 2 fp32 FMAs per instruction)
__device__ __forceinline__ unsigned long long ffma2(unsigned long long a,
                                                    unsigned long long b,
                                                    unsigned long long c) {
    unsigned long long d;
    asm("fma.rn.f32x2 %0, %1, %2, %3;" : "=l"(d) : "l"(a), "l"(b), "l"(c));
    return d;
}
__device__ __forceinline__ unsigned long long pack2(float x, float y) {
    unsigned long long d;
    asm("mov.b64 %0, {%1, %2};" : "=l"(d) : "f"(x), "f"(y));
    return d;
}
__device__ __forceinline__ float2 unpack2(unsigned long long v) {
    float x, y;
    asm("mov.b64 {%0, %1}, %2;" : "=f"(x), "=f"(y) : "l"(v));
    return make_float2(x, y);
}

// ============================================================================
// Kernel P: ONE pass over x -> qkv_t partials, V, spatial k/v partials.
// Grid: 128 blocks = (bc 0..63) x (n-half 0..1), 256 threads, 8 n each.
// ============================================================================
__global__ __launch_bounds__(256) void kproj(const float* __restrict__ x,
                                             const float* __restrict__ w_qkv_s,
                                             const float* __restrict__ w_qkv_t) {
    const float EPS = 1e-10f;

    int blk  = blockIdx.x;
    int bc   = blk >> 1;
    int half = blk & 1;
    int b    = bc >> 4, c = bc & 15;
    int tid  = threadIdx.x;
    int lane = tid & 31, wid = tid >> 5;   // 8 warps

    __shared__ unsigned long long sws2[NK * T_];   // w_qkv_s as duplicated pairs
    __shared__ float4 s_part[8 * NK * T_];         // per-warp 4-coset partials
    __shared__ float s_sp[8 * 6];                  // per-warp spatial partials

    if (tid < NK * T_) {
        float w = w_qkv_s[tid];
        sws2[tid] = pack2(w, w);
    }
    __syncthreads();

    int n0 = half * 2048 + tid * 8;
    const float* xb = x + bc * T_ * HW_;

    // loop-invariant w_qkv_t columns (8 n) as packed pairs
    unsigned long long wtp[NK][4];
#pragma unroll
    for (int k = 0; k < NK; k++) {
        float4 wa = *reinterpret_cast<const float4*>(w_qkv_t + k * HW_ + n0);
        float4 wb = *reinterpret_cast<const float4*>(w_qkv_t + k * HW_ + n0 + 4);
        wtp[k][0] = pack2(wa.x, wa.y);
        wtp[k][1] = pack2(wa.z, wa.w);
        wtp[k][2] = pack2(wb.x, wb.y);
        wtp[k][3] = pack2(wb.z, wb.w);
    }

    unsigned long long qsp[NK][4];
#pragma unroll
    for (int k = 0; k < NK; k++)
#pragma unroll
        for (int p = 0; p < 4; p++) qsp[k][p] = 0ULL;

    const unsigned long long zero64 = 0ULL;
    float* s_partf = reinterpret_cast<float*>(s_part);

    for (int t = 0; t < T_; t++) {
        float4 xa = *reinterpret_cast<const float4*>(xb + t * HW_ + n0);
        float4 xc = *reinterpret_cast<const float4*>(xb + t * HW_ + n0 + 4);
        unsigned long long x0 = pack2(xa.x, xa.y);
        unsigned long long x1 = pack2(xa.z, xa.w);
        unsigned long long x2 = pack2(xc.x, xc.y);
        unsigned long long x3 = pack2(xc.z, xc.w);
#pragma unroll
        for (int k = 0; k < NK; k++) {
            unsigned long long wd = sws2[k * T_ + t];   // LDS.64 broadcast
            qsp[k][0] = ffma2(wd, x0, qsp[k][0]);
            qsp[k][1] = ffma2(wd, x1, qsp[k][1]);
            qsp[k][2] = ffma2(wd, x2, qsp[k][2]);
            qsp[k][3] = ffma2(wd, x3, qsp[k][3]);
            unsigned long long acc =
                ffma2(x0, wtp[k][0],
                ffma2(x1, wtp[k][1],
                ffma2(x2, wtp[k][2],
                ffma2(x3, wtp[k][3], zero64))));
            float2 f = unpack2(acc);
            float pt = f.x + f.y;
            pt = warpSum4(pt);                          // 3 SHFL
            if (lane < 4)                               // 1 predicated STS
                s_partf[((wid * NK + k) * T_ + t) * 4 + lane] = pt;
        }
    }

    // unpack qkv_s values for this thread's 8 n
    float qf[NK][8];
#pragma unroll
    for (int k = 0; k < NK; k++)
#pragma unroll
        for (int p = 0; p < 4; p++) {
            float2 f = unpack2(qsp[k][p]);
            qf[k][2 * p + 0] = f.x;
            qf[k][2 * p + 1] = f.y;
        }

    // ---- fused spatial epilogue (all from registers) ----
    // V: pairwise softmax of (qf[0],qf[1]) over d, +eps, sqrt
    float v0[8], v1[8];
#pragma unroll
    for (int j = 0; j < 8; j++) {
        float e0 = expf(qf[0][j]), e1 = expf(qf[1][j]);
        float inv = 1.f / (e0 + e1);
        v0[j] = sqrtf(fmaf(e0, inv, EPS));
        v1[j] = sqrtf(fmaf(e1, inv, EPS));
    }
    {
        float* gv0 = g_V + (b * M_ + c * 2 + 0) * HW_ + n0;
        float* gv1 = g_V + (b * M_ + c * 2 + 1) * HW_ + n0;
        *reinterpret_cast<float4*>(gv0)     = make_float4(v0[0], v0[1], v0[2], v0[3]);
        *reinterpret_cast<float4*>(gv0 + 4) = make_float4(v0[4], v0[5], v0[6], v0[7]);
        *reinterpret_cast<float4*>(gv1)     = make_float4(v1[0], v1[1], v1[2], v1[3]);
        *reinterpret_cast<float4*>(gv1 + 4) = make_float4(v1[4], v1[5], v1[6], v1[7]);
    }

    // spatial k/v partials: S_d = sum exp(ks_d), P[d][e] = sum sqrt(exp(ks_d))*sqrt(vs_e)
    float S0 = 0.f, S1 = 0.f, P00 = 0.f, P01 = 0.f, P10 = 0.f, P11 = 0.f;
#pragma unroll
    for (int j = 0; j < 8; j++) {
        float ek0 = expf(qf[2][j]), ek1 = expf(qf[3][j]);
        float sv0 = sqrtf(qf[4][j]), sv1 = sqrtf(qf[5][j]);
        S0 += ek0; S1 += ek1;
        float r0 = sqrtf(ek0), r1 = sqrtf(ek1);
        P00 = fmaf(r0, sv0, P00); P01 = fmaf(r0, sv1, P01);
        P10 = fmaf(r1, sv0, P10); P11 = fmaf(r1, sv1, P11);
    }
    S0 = warpSumAll(S0); S1 = warpSumAll(S1);
    P00 = warpSumAll(P00); P01 = warpSumAll(P01);
    P10 = warpSumAll(P10); P11 = warpSumAll(P11);
    if (lane == 0) {
        s_sp[wid * 6 + 0] = S0;  s_sp[wid * 6 + 1] = S1;
        s_sp[wid * 6 + 2] = P00; s_sp[wid * 6 + 3] = P01;
        s_sp[wid * 6 + 4] = P10; s_sp[wid * 6 + 5] = P11;
    }

    __syncthreads();
    // combine 8 warps x 4 cosets per (k,t) in fixed order
    if (tid < NK * T_) {
        float v = 0.f;
#pragma unroll
        for (int w = 0; w < 8; w++) {
            float4 f = s_part[w * NK * T_ + tid];
            v += (f.x + f.y) + (f.z + f.w);
        }
        g_qkv_t_part[(bc * 2 + half) * NK * T_ + tid] = v;
    }
    if (tid < 6) {
        float v = 0.f;
#pragma unroll
        for (int w = 0; w < 8; w++) v += s_sp[w * 6 + tid];
        g_sp[(bc * 2 + half) * 6 + tid] = v;
    }
}

// ============================================================================
// Kernel S2: combine partials, temporal branch, ctx, folded G matrices.
// Grid: 64 blocks = (b,c), 192 threads.
// ============================================================================
__global__ __launch_bounds__(192) void kstage2(const float* __restrict__ w_out_s,
                                               const float* __restrict__ w_out_t) {
    const float EPS   = 1e-10f;
    const float SCALE = 0.8408964152537145f;  // 2^-0.25

    int bc = blockIdx.x;
    int b = bc >> 4, c = bc & 15;
    int tid = threadIdx.x;
    int lane = tid & 31, wid = tid >> 5;

    __shared__ float s_qkvt[NK * T_];
    __shared__ float s_A[4];    // A[d][e]
    __shared__ float s_ctx[4];

    // combine the 2 n-half partials of qkv_t
    if (tid < NK * T_) {
        float v = g_qkv_t_part[(bc * 2 + 0) * NK * T_ + tid]
                + g_qkv_t_part[(bc * 2 + 1) * NK * T_ + tid];
        s_qkvt[tid] = v;
    }
    __syncthreads();

    // ---- temporal branch: warp 0, lane = t ----
    if (wid == 0) {
        int t = lane;
        float qt0 = s_qkvt[0 * T_ + t], qt1 = s_qkvt[1 * T_ + t];
        float kt0 = s_qkvt[2 * T_ + t], kt1 = s_qkvt[3 * T_ + t];
        float vt0 = s_qkvt[4 * T_ + t], vt1 = s_qkvt[5 * T_ + t];

        float e0 = expf(qt0), e1 = expf(qt1);
        float inv = 1.f / (e0 + e1);
        g_U[(b * M_ + c * 2 + 0) * T_ + t] = sqrtf(e0 * inv + EPS);
        g_U[(b * M_ + c * 2 + 1) * T_ + t] = sqrtf(e1 * inv + EPS);

        float ek0 = expf(kt0), ek1 = expf(kt1);
        float St0 = warpSumAll(ek0), St1 = warpSumAll(ek1);
        float r0 = sqrtf(ek0 / St0 + EPS), r1 = sqrtf(ek1 / St1 + EPS);
        float sv0 = sqrtf(vt0), sv1 = sqrtf(vt1);
        float a00 = warpSumAll(r0 * sv0);
        float a01 = warpSumAll(r0 * sv1);
        float a10 = warpSumAll(r1 * sv0);
        float a11 = warpSumAll(r1 * sv1);
        if (lane == 0) { s_A[0] = a00; s_A[1] = a01; s_A[2] = a10; s_A[3] = a11; }
    }
    __syncthreads();

    // ---- spatial combine + ctx (single thread) ----
    if (tid == 0) {
        float S0 = 0.f, S1 = 0.f, P[4] = {0.f, 0.f, 0.f, 0.f};
#pragma unroll
        for (int h = 0; h < 2; h++) {
            const float* sp = g_sp + (bc * 2 + h) * 6;
            S0 += sp[0]; S1 += sp[1];
            P[0] += sp[2]; P[1] += sp[3]; P[2] += sp[4]; P[3] += sp[5];
        }
        float i0 = rsqrtf(S0), i1 = rsqrtf(S1);
        s_ctx[0] = SCALE * s_A[0] * P[0] * i0;
        s_ctx[1] = SCALE * s_A[1] * P[1] * i0;
        s_ctx[2] = SCALE * s_A[2] * P[2] * i1;
        s_ctx[3] = SCALE * s_A[3] * P[3] * i1;
    }
    __syncthreads();

    // fold output projection: G[c', m=(c,d)] = scale * sum_e w_out[c', c*2+e] * ctx[d,e]
    if (tid < 16) {
        int cp = tid;
        float ws0 = w_out_s[cp * M_ + c * 2 + 0], ws1 = w_out_s[cp * M_ + c * 2 + 1];
        float wt0 = w_out_t[cp * M_ + c * 2 + 0], wt1 = w_out_t[cp * M_ + c * 2 + 1];
#pragma unroll
        for (int d = 0; d < 2; d++) {
            float c0 = s_ctx[d * 2 + 0], c1 = s_ctx[d * 2 + 1];
            g_Gs[(b * C_ + cp) * M_ + c * 2 + d] = SCALE * (ws0 * c0 + ws1 * c1);
            g_Gt[(b * C_ + cp) * M_ + c * 2 + d] = SCALE * (wt0 * c0 + wt1 * c1);
        }
    }
}

// ============================================================================
// Kernel O: out[b,c',t,n] = sqrt( (Ws[c',:]·V[:,n]) * (Wt[c',:]·V[:,n]) )
// where Ws[c',m] = Gs[c',m]*U[m,t]  (per (b,t) block).
// Grid: (128 = b*t, 4 n-chunks), 256 threads, 4 n each. Packed f32x2 FMAs.
// Interleaved {Ws,Wt} pairs -> one LDS.128 per (cp,m) instead of two LDS.64.
// ============================================================================
__global__ __launch_bounds__(256) void kout(float* __restrict__ out) {
    int bt = blockIdx.x;
    int b = bt >> 5, t = bt & 31;
    int tid = threadIdx.x;
    int n0 = blockIdx.y * 1024 + tid * 4;

    __shared__ ulonglong2 sW[C_ * M_];  // {Ws dup-pair, Wt dup-pair} per (cp,m)

    for (int i = tid; i < C_ * M_; i += 256) {
        int cp = i >> 5, m = i & 31;
        float u = g_U[(b * M_ + m) * T_ + t];
        float a = g_Gs[(b * C_ + cp) * M_ + m] * u;
        float d = g_Gt[(b * C_ + cp) * M_ + m] * u;
        ulonglong2 p;
        p.x = pack2(a, a);
        p.y = pack2(d, d);
        sW[i] = p;
    }
    __syncthreads();

    const float* Vb = g_V + b * M_ * HW_;

#pragma unroll
    for (int chunk = 0; chunk < 2; chunk++) {
        unsigned long long as[8][2], at[8][2];
#pragma unroll
        for (int cc = 0; cc < 8; cc++) {
            as[cc][0] = 0ULL; as[cc][1] = 0ULL;
            at[cc][0] = 0ULL; at[cc][1] = 0ULL;
        }
#pragma unroll 4
        for (int m = 0; m < M_; m++) {
            float4 v = *reinterpret_cast<const float4*>(Vb + m * HW_ + n0);
            unsigned long long v01 = pack2(v.x, v.y);
            unsigned long long v23 = pack2(v.z, v.w);
#pragma unroll
            for (int cc = 0; cc < 8; cc++) {
                ulonglong2 w = sW[(chunk * 8 + cc) * M_ + m];
                as[cc][0] = ffma2(w.x, v01, as[cc][0]);
                as[cc][1] = ffma2(w.x, v23, as[cc][1]);
                at[cc][0] = ffma2(w.y, v01, at[cc][0]);
                at[cc][1] = ffma2(w.y, v23, at[cc][1]);
            }
        }
#pragma unroll
        for (int cc = 0; cc < 8; cc++) {
            int cp = chunk * 8 + cc;
            float2 s0 = unpack2(as[cc][0]), s1 = unpack2(as[cc][1]);
            float2 t0 = unpack2(at[cc][0]), t1 = unpack2(at[cc][1]);
            float4 o;
            o.x = sqrtf(s0.x * t0.x);
            o.y = sqrtf(s0.y * t0.y);
            o.z = sqrtf(s1.x * t1.x);
            o.w = sqrtf(s1.y * t1.y);
            *reinterpret_cast<float4*>(out + ((b * C_ + cp) * T_ + t) * HW_ + n0) = o;
        }
    }
}

// ============================================================================
extern "C" void kernel_launch(void* const* d_in, const int* in_sizes, int n_in,
                              void* d_out, int out_size) {
    (void)in_sizes; (void)n_in; (void)out_size;
    const float* x       = (const float*)d_in[0];
    const float* w_qkv_s = (const float*)d_in[1];
    const float* w_qkv_t = (const float*)d_in[2];
    const float* w_out_s = (const float*)d_in[3];
    const float* w_out_t = (const float*)d_in[4];
    float* out = (float*)d_out;

    kproj<<<128, 256>>>(x, w_qkv_s, w_qkv_t);
    kstage2<<<64, 192>>>(w_out_s, w_out_t);
    kout<<<dim3(128, 4), 256>>>(out);
}